// round 15
// baseline (speedup 1.0000x reference)
#include <cuda_runtime.h>
#include <cuda_fp16.h>
#include <cstdint>

#define B_    2
#define T_    2048
#define NH    16
#define DM    2048
#define DQ    682
#define DQP   704
#define DKV   1024
#define DCKV  1088
#define BT    4096
#define NCOMB 1792            // 704 (padded Wdq) + 1088 (Wdkv)

// ---------------- float scratch ----------------
#define SZ_CQKV  (BT * NCOMB)
#define OFF_CQKV 0
#define OFF_BCMB (OFF_CQKV + SZ_CQKV)
#define SZ_FTOT  (OFF_BCMB + NCOMB)
__device__ __align__(1024) float g_scratch[SZ_FTOT];

// ---------------- half scratch ----------------
#define HSZ_X     (BT * DM)
#define HSZ_WCOMB (NCOMB * DM)
#define HSZ_WUQ   (2048 * DQP)
#define HSZ_WUKV  (3072 * DKV)
#define HSZ_WO    (DM * DM)
#define HSZ_CQ    (BT * DQP)
#define HSZ_CKV   (BT * DKV)
#define HSZ_QLIN  (BT * DM)
#define HSZ_KV    (BT * 3072)
#define HSZ_F     (32 * T_ * 128)
#define HOFF_X     0
#define HOFF_WCOMB (HOFF_X + HSZ_X)
#define HOFF_WUQ   (HOFF_WCOMB + HSZ_WCOMB)
#define HOFF_WUKV  (HOFF_WUQ + HSZ_WUQ)
#define HOFF_WO    (HOFF_WUKV + HSZ_WUKV)
#define HOFF_CQ    (HOFF_WO + HSZ_WO)
#define HOFF_CKV   (HOFF_CQ + HSZ_CQ)
#define HOFF_QLIN  (HOFF_CKV + HSZ_CKV)
#define HOFF_KV    (HOFF_QLIN + HSZ_QLIN)
#define HOFF_QF    (HOFF_KV + HSZ_KV)
#define HOFF_KF    (HOFF_QF + HSZ_F)
#define HOFF_VT    (HOFF_KF + HSZ_F)
#define HOFF_Y     (HOFF_VT + HSZ_F)
#define HSZ_TOT    (HOFF_Y + HSZ_F)
__device__ __align__(1024) __half g_hscr[HSZ_TOT];

// ---------------- helpers ----------------
__device__ __forceinline__ float ex2(float x) {
    float r; asm("ex2.approx.f32 %0,%1;" : "=f"(r) : "f"(x)); return r;
}
__device__ __forceinline__ uint32_t f2h2(float hi, float lo) {
    uint32_t u; asm("cvt.rn.f16x2.f32 %0,%1,%2;" : "=r"(u) : "f"(hi), "f"(lo)); return u;
}
__device__ __forceinline__ void mma_f16(float* d, const uint32_t* a, const uint32_t* b) {
    asm volatile(
        "mma.sync.aligned.m16n8k16.row.col.f32.f16.f16.f32 "
        "{%0,%1,%2,%3}, {%4,%5,%6,%7}, {%8,%9}, {%0,%1,%2,%3};\n"
        : "+f"(d[0]), "+f"(d[1]), "+f"(d[2]), "+f"(d[3])
        : "r"(a[0]), "r"(a[1]), "r"(a[2]), "r"(a[3]), "r"(b[0]), "r"(b[1]));
}
__device__ __forceinline__ void ldsm4(uint32_t* r, uint32_t addr) {
    asm volatile("ldmatrix.sync.aligned.m8n8.x4.shared.b16 {%0,%1,%2,%3}, [%4];"
        : "=r"(r[0]), "=r"(r[1]), "=r"(r[2]), "=r"(r[3]) : "r"(addr));
}
__device__ __forceinline__ void cp16(uint32_t dst, const void* src) {
    asm volatile("cp.async.cg.shared.global [%0], [%1], 16;" :: "r"(dst), "l"(src));
}
__device__ __forceinline__ void cp_commit() { asm volatile("cp.async.commit_group;"); }
template<int N> __device__ __forceinline__ void cp_wait() {
    asm volatile("cp.async.wait_group %0;" :: "n"(N));
}

// ---------------- fp16 GEMM: C = A @ W^T + bias ----------------
// BM=128, BN=128, BK=32 halves, 3-stage cp.async, 8 warps, warp tile 64x32, ldmatrix.x4.
#define G_ST 3
#define AST (128 * 20)
#define GSMB (2 * AST * 4 * G_ST)

template<typename OT>
__global__ void __launch_bounds__(256, 2) gemm_h(
    const __half* __restrict__ A, const __half* __restrict__ W,
    const float* __restrict__ bias, OT* __restrict__ C,
    int M, int N, int K, int lda, int ldc)
{
    extern __shared__ uint32_t smu[];
    const uint32_t smA_u = (uint32_t)__cvta_generic_to_shared(smu);
    const uint32_t smB_u = smA_u + G_ST * AST * 4;
    const int tid = threadIdx.x;
    const int m0 = blockIdx.y * 128;
    const int n0 = blockIdx.x * 128;
    const int warp = tid >> 5, lane = tid & 31;
    const int wm = warp & 1, wn = warp >> 1;
    const int gid = lane >> 2, tig = lane & 3;
    const int g = lane >> 3, lr = lane & 7;
    const int arow = (g & 1) * 8 + lr, achk = g >> 1;
    const int brow = (g >> 1) * 8 + lr, bchk = g & 1;
    uint32_t aoff[4], boff[2];
#pragma unroll
    for (int mt = 0; mt < 4; mt++)
        aoff[mt] = (uint32_t)((wm * 64 + mt * 16 + arow) * 80 + achk * 16);
#pragma unroll
    for (int ntp = 0; ntp < 2; ntp++)
        boff[ntp] = (uint32_t)((wn * 32 + ntp * 16 + brow) * 80 + bchk * 16);

    float c[4][4][4];
#pragma unroll
    for (int i = 0; i < 4; i++)
#pragma unroll
        for (int j = 0; j < 4; j++)
#pragma unroll
            for (int r = 0; r < 4; r++) c[i][j][r] = 0.f;

    const int ntile = K / 32;

#define LOAD_STAGE(st, k0) do {                                               \
        const uint32_t ab = smA_u + (st) * (AST * 4);                         \
        const uint32_t bb2 = smB_u + (st) * (AST * 4);                        \
        _Pragma("unroll")                                                     \
        for (int ii = 0; ii < 2; ii++) {                                      \
            const int cid = tid + ii * 256;                                   \
            const int r = cid >> 2, ch = cid & 3;                             \
            cp16(ab + r * 80 + ch * 16,                                       \
                 A + (size_t)(m0 + r) * lda + (k0) + ch * 8);                 \
            cp16(bb2 + r * 80 + ch * 16,                                      \
                 W + (size_t)(n0 + r) * K + (k0) + ch * 8);                   \
        }                                                                     \
    } while (0)

    LOAD_STAGE(0, 0);  cp_commit();
    LOAD_STAGE(1, 32); cp_commit();

    for (int kt = 0; kt < ntile; kt++) {
        cp_wait<1>();
        __syncthreads();
        if (kt + 2 < ntile) { LOAD_STAGE((kt + 2) % 3, (kt + 2) * 32); }
        cp_commit();
        const uint32_t Ab = smA_u + (kt % 3) * (AST * 4);
        const uint32_t Bb = smB_u + (kt % 3) * (AST * 4);
#pragma unroll
        for (int ks = 0; ks < 2; ks++) {
            uint32_t amt[4][4], bb[2][4];
#pragma unroll
            for (int mt = 0; mt < 4; mt++) ldsm4(amt[mt], Ab + aoff[mt] + ks * 32);
#pragma unroll
            for (int ntp = 0; ntp < 2; ntp++) ldsm4(bb[ntp], Bb + boff[ntp] + ks * 32);
#pragma unroll
            for (int mt = 0; mt < 4; mt++)
#pragma unroll
                for (int nt = 0; nt < 4; nt++)
                    mma_f16(c[mt][nt], amt[mt], &bb[nt >> 1][(nt & 1) * 2]);
        }
    }
#undef LOAD_STAGE

#pragma unroll
    for (int mt = 0; mt < 4; mt++) {
        const int row = m0 + wm * 64 + mt * 16 + gid;
#pragma unroll
        for (int nt = 0; nt < 4; nt++) {
            const int col = n0 + wn * 32 + nt * 8 + 2 * tig;
            if (col >= ldc) continue;
            const float b0 = bias[col];
            const float b1 = bias[col + 1];
            const float r00 = c[mt][nt][0] + b0;
            const float r01 = c[mt][nt][1] + b1;
            const float r10 = c[mt][nt][2] + b0;
            const float r11 = c[mt][nt][3] + b1;
            if constexpr (sizeof(OT) == 4) {
                *(float2*)((float*)C + (size_t)row * ldc + col) = make_float2(r00, r01);
                *(float2*)((float*)C + (size_t)(row + 8) * ldc + col) = make_float2(r10, r11);
            } else {
                *(uint32_t*)((__half*)C + (size_t)row * ldc + col) = f2h2(r01, r00);
                *(uint32_t*)((__half*)C + (size_t)(row + 8) * ldc + col) = f2h2(r11, r10);
            }
        }
    }
}

// ---------------- conversion / prep kernels ----------------
__global__ void f2h_copy(const float* __restrict__ src, __half* __restrict__ dst, int n4)
{
    const int i = blockIdx.x * 256 + threadIdx.x;
    if (i >= n4) return;
    float4 v = ((const float4*)src)[i];
    uint2 u;
    u.x = f2h2(v.y, v.x);
    u.y = f2h2(v.w, v.z);
    ((uint2*)dst)[i] = u;
}

__global__ void f2h_weights(const float* w0, __half* d0, int n0,
                            const float* w1, __half* d1, int n1)
{
    const int i = blockIdx.x * 256 + threadIdx.x;
    const float* s; __half* d; int n;
    if (blockIdx.y == 0) { s = w0; d = d0; n = n0; }
    else                 { s = w1; d = d1; n = n1; }
    if (i >= n) return;
    float4 v = ((const float4*)s)[i];
    uint2 u;
    u.x = f2h2(v.y, v.x);
    u.y = f2h2(v.w, v.z);
    ((uint2*)d)[i] = u;
}

__global__ void pack_comb(const float* __restrict__ wdq, const float* __restrict__ wdq_b,
                          const float* __restrict__ wdkv, const float* __restrict__ wdkv_b,
                          __half* __restrict__ wc, float* __restrict__ bc)
{
    const int idx = blockIdx.x * 256 + threadIdx.x;
    if (idx < NCOMB) {
        float bv = 0.f;
        if (idx < DQ) bv = wdq_b[idx];
        else if (idx >= DQP) bv = wdkv_b[idx - DQP];
        bc[idx] = bv;
    }
    if (idx >= NCOMB * DM) return;
    const int r = idx >> 11, k = idx & 2047;
    float v = 0.f;
    if (r < DQ) v = wdq[r * DM + k];
    else if (r >= DQP) v = wdkv[(r - DQP) * DM + k];
    wc[idx] = __float2half(v);
}

__global__ void pack_wuq(const float* __restrict__ w, __half* __restrict__ wp)
{
    const int idx = blockIdx.x * 256 + threadIdx.x;
    if (idx >= 2048 * DQP) return;
    const int n = idx / DQP, k = idx - n * DQP;
    wp[idx] = (k < DQ) ? __float2half(w[n * DQ + k]) : __float2half(0.f);
}

__global__ void ln_kernel(const float* __restrict__ X, int stride, int n,
                          const float* __restrict__ g, const float* __restrict__ bb,
                          __half* __restrict__ out, int ostride)
{
    const int row = blockIdx.x;
    const float* xr = X + (size_t)row * stride;
    __half* orow = out + (size_t)row * ostride;
    const int tid = threadIdx.x;
    float s = 0.f, ss = 0.f;
    for (int i = tid; i < n; i += 256) { float v = xr[i]; s += v; ss += v * v; }
#pragma unroll
    for (int o = 16; o > 0; o >>= 1) {
        s  += __shfl_down_sync(0xffffffffu, s, o);
        ss += __shfl_down_sync(0xffffffffu, ss, o);
    }
    __shared__ float rs[8], rss[8];
    __shared__ float sh_mu, sh_rstd;
    if ((tid & 31) == 0) { rs[tid >> 5] = s; rss[tid >> 5] = ss; }
    __syncthreads();
    if (tid == 0) {
        float ts = 0.f, tss = 0.f;
#pragma unroll
        for (int i = 0; i < 8; i++) { ts += rs[i]; tss += rss[i]; }
        const float mu = ts / n;
        sh_mu = mu;
        sh_rstd = rsqrtf(tss / n - mu * mu + 1e-5f);
    }
    __syncthreads();
    const float mu = sh_mu, rstd = sh_rstd;
    for (int i = tid; i < n; i += 256)
        orow[i] = __float2half((xr[i] - mu) * rstd * g[i] + bb[i]);
    for (int i = n + tid; i < ostride; i += 256)
        orow[i] = __float2half(0.f);
}

__global__ void prep_q_kernel(const __half* __restrict__ qlin, __half* __restrict__ qf)
{
    const int idx = blockIdx.x * blockDim.x + threadIdx.x;
    const int d = idx & 127;
    const int t = (idx >> 7) & (T_ - 1);
    const int bh = idx >> 18;
    const int b = bh >> 4, h = bh & 15;
    const __half* qrow = qlin + (size_t)(b * T_ + t) * DM + h * 128;
    float outv;
    if (d < 64) {
        outv = __half2float(qrow[d]);
    } else {
        const int i = (d - 64) & 31;
        const float inv = __expf(-(float)i * 0.2878231366242557f);
        float sn, c;
        __sincosf((float)h * inv, &sn, &c);
        const float x1 = __half2float(qrow[64 + i]);
        const float x2 = __half2float(qrow[96 + i]);
        outv = (d < 96) ? (x1 * c + x2 * sn) : (x2 * c - x1 * sn);
    }
    qf[idx] = __float2half(outv * (0.08838834764831845f * 1.4426950408889634f));
}

__global__ void prep_kv_kernel(const __half* __restrict__ kv, const float* __restrict__ krs,
                               __half* __restrict__ kf, __half* __restrict__ vt)
{
    __shared__ __half vs[32][136];
    const int bh = blockIdx.y, tile = blockIdx.x;
    const int b = bh >> 4, h = bh & 15;
    const int tid = threadIdx.x;
    for (int e = tid; e < 32 * 128; e += 256) {
        const int tl = e >> 7, d = e & 127;
        const int t = tile * 32 + tl;
        const size_t row = (size_t)(b * T_ + t);
        const __half* kvrow = kv + row * 3072 + h * 192;
        const __half kvv = (d < 64) ? kvrow[d] : __float2half(krs[row * NCOMB + (d - 64)]);
        kf[((size_t)bh * T_ + t) * 128 + d] = kvv;
        vs[tl][d] = kvrow[64 + d];
    }
    __syncthreads();
    for (int c = tid; c < 512; c += 256) {
        const int d = c >> 2, q = c & 3;
        uint4 u;
        __half* tgt = (__half*)&u;
#pragma unroll
        for (int j = 0; j < 8; j++) tgt[j] = vs[8 * q + j][d];
        *(uint4*)(vt + ((size_t)bh * 128 + d) * T_ + tile * 32 + 8 * q) = u;
    }
}

// ---------------- fp16 causal flash attention with ldmatrix ----------------
#define KROWB 272
#define VROWB 144
#define SMK_B (64 * KROWB)
#define SMV_B (128 * VROWB)
#define ASM_TOT (SMK_B + SMV_B)

__global__ __launch_bounds__(128, 3) void attn_h(
    const __half* __restrict__ qf, const __half* __restrict__ kf,
    const __half* __restrict__ vt, __half* __restrict__ y)
{
    extern __shared__ uint32_t asw[];
    const int tid = threadIdx.x;
    const int warp = tid >> 5, lane = tid & 31;
    const int gid = lane >> 2, tig = lane & 3;
    const int g = lane >> 3, lr = lane & 7;
    const int arow = (g & 1) * 8 + lr, achk = g >> 1;
    const int brow = (g >> 1) * 8 + lr, bchk = g & 1;
    const int qt = (int)gridDim.x - 1 - (int)blockIdx.x;
    const int bh = blockIdx.y;
    const int qb = qt * 64;
    const __half* Qg = qf + ((size_t)bh * T_ + qb) * 128;
    const __half* Kg = kf + (size_t)bh * T_ * 128;
    const __half* Vg = vt + (size_t)bh * 128 * T_;
    const uint32_t smb = (uint32_t)__cvta_generic_to_shared(asw);
    const uint32_t ks_u = smb;
    const uint32_t vs_u = smb + SMK_B;
    const uint32_t ka_off = (uint32_t)((warp * 16 + arow) * KROWB + achk * 16);
    const uint32_t kb_off = (uint32_t)(brow * KROWB + bchk * 16);
    const uint32_t vb_off = (uint32_t)(brow * VROWB + bchk * 16);

#pragma unroll
    for (int i = 0; i < 8; i++) {
        const int c = tid + i * 128;
        const int r = c >> 4, ch = c & 15;
        cp16(ks_u + r * KROWB + ch * 16, Qg + (size_t)r * 128 + ch * 8);
    }
    cp_commit(); cp_wait<0>();
    __syncthreads();
    uint32_t qa[8][4];
#pragma unroll
    for (int kk = 0; kk < 8; kk++) ldsm4(qa[kk], ks_u + ka_off + kk * 32);
    __syncthreads();

#define LOAD_K(kt) do {                                                       \
        const __half* Kt = Kg + (size_t)(kt) * 64 * 128;                      \
        _Pragma("unroll")                                                     \
        for (int i = 0; i < 8; i++) {                                         \
            const int c = tid + i * 128;                                      \
            const int r = c >> 4, ch = c & 15;                                \
            cp16(ks_u + r * KROWB + ch * 16, Kt + (size_t)r * 128 + ch * 8);  \
        }                                                                     \
    } while (0)
#define LOAD_V(kt) do {                                                       \
        _Pragma("unroll")                                                     \
        for (int i = 0; i < 8; i++) {                                         \
            const int c = tid + i * 128;                                      \
            const int r = c >> 3, ch = c & 7;                                 \
            cp16(vs_u + r * VROWB + ch * 16,                                  \
                 Vg + (size_t)r * T_ + (kt) * 64 + ch * 8);                   \
        }                                                                     \
    } while (0)

    LOAD_K(0); cp_commit();
    LOAD_V(0); cp_commit();

    float o[16][4];
#pragma unroll
    for (int i = 0; i < 16; i++)
#pragma unroll
        for (int j = 0; j < 4; j++) o[i][j] = 0.f;
    float l0 = 0.f, l1 = 0.f;
    const int row0 = qb + warp * 16 + gid;
    const int row1 = row0 + 8;

    for (int kt = 0; kt <= qt; kt++) {
        cp_wait<1>();
        __syncthreads();

        float s[8][4];
#pragma unroll
        for (int nt = 0; nt < 8; nt++)
#pragma unroll
            for (int r = 0; r < 4; r++) s[nt][r] = 0.f;
#pragma unroll
        for (int ntp = 0; ntp < 4; ntp++) {
            const uint32_t base = ks_u + kb_off + (uint32_t)(ntp * 16 * KROWB);
#pragma unroll
            for (int kk = 0; kk < 8; kk++) {
                uint32_t kb[4];
                ldsm4(kb, base + kk * 32);
                mma_f16(s[2 * ntp],     qa[kk], &kb[0]);
                mma_f16(s[2 * ntp + 1], qa[kk], &kb[2]);
            }
        }
        __syncthreads();
        if (kt < qt) { LOAD_K(kt + 1); }
        cp_commit();

        if (kt == qt) {
            const int kb = kt * 64;
#pragma unroll
            for (int nt = 0; nt < 8; nt++) {
                const int col = kb + 8 * nt + 2 * tig;
                if (col > row0)     s[nt][0] = -1e30f;
                if (col + 1 > row0) s[nt][1] = -1e30f;
                if (col > row1)     s[nt][2] = -1e30f;
                if (col + 1 > row1) s[nt][3] = -1e30f;
            }
        }
        uint32_t ph[8][2];
#pragma unroll
        for (int nt = 0; nt < 8; nt++) {
            const float p0 = ex2(s[nt][0]);
            const float p1 = ex2(s[nt][1]);
            const float p2 = ex2(s[nt][2]);
            const float p3 = ex2(s[nt][3]);
            l0 += p0 + p1;
            l1 += p2 + p3;
            ph[nt][0] = f2h2(p1, p0);
            ph[nt][1] = f2h2(p3, p2);
        }

        cp_wait<1>();
        __syncthreads();
#pragma unroll
        for (int kk = 0; kk < 4; kk++) {
            uint32_t pa[4];
            pa[0] = ph[2 * kk][0];
            pa[1] = ph[2 * kk][1];
            pa[2] = ph[2 * kk + 1][0];
            pa[3] = ph[2 * kk + 1][1];
#pragma unroll
            for (int ntp = 0; ntp < 8; ntp++) {
                uint32_t vb[4];
                ldsm4(vb, vs_u + vb_off + (uint32_t)(ntp * 16 * VROWB) + kk * 32);
                mma_f16(o[2 * ntp],     pa, &vb[0]);
                mma_f16(o[2 * ntp + 1], pa, &vb[2]);
            }
        }
        __syncthreads();
        if (kt < qt) { LOAD_V(kt + 1); }
        cp_commit();
    }
#undef LOAD_K
#undef LOAD_V

    l0 += __shfl_xor_sync(0xffffffffu, l0, 1);
    l0 += __shfl_xor_sync(0xffffffffu, l0, 2);
    l1 += __shfl_xor_sync(0xffffffffu, l1, 1);
    l1 += __shfl_xor_sync(0xffffffffu, l1, 2);
    const float i0 = 1.f / l0, i1 = 1.f / l1;
    const int b = bh >> 4, h = bh & 15;
    __half* y0 = y + ((size_t)(b * T_ + row0)) * 2048 + h * 128;
    __half* y1 = y + ((size_t)(b * T_ + row1)) * 2048 + h * 128;
#pragma unroll
    for (int nt = 0; nt < 16; nt++) {
        const int col = 8 * nt + 2 * tig;
        *(uint32_t*)(y0 + col) = f2h2(o[nt][1] * i0, o[nt][0] * i0);
        *(uint32_t*)(y1 + col) = f2h2(o[nt][3] * i1, o[nt][2] * i1);
    }
}

// ---------------- launch ----------------
extern "C" void kernel_launch(void* const* d_in, const int* in_sizes, int n_in,
                              void* d_out, int out_size)
{
    const float* x      = (const float*)d_in[0];
    const float* Wdq_w  = (const float*)d_in[1];
    const float* Wdq_b  = (const float*)d_in[2];
    const float* qn_g   = (const float*)d_in[3];
    const float* qn_b   = (const float*)d_in[4];
    const float* Wuq_w  = (const float*)d_in[5];
    const float* Wuq_b  = (const float*)d_in[6];
    const float* Wdkv_w = (const float*)d_in[7];
    const float* Wdkv_b = (const float*)d_in[8];
    const float* kvn_g  = (const float*)d_in[9];
    const float* kvn_b  = (const float*)d_in[10];
    const float* Wukv_w = (const float*)d_in[11];
    const float* Wukv_b = (const float*)d_in[12];
    const float* Wo_w   = (const float*)d_in[13];
    const float* Wo_b   = (const float*)d_in[14];
    float* out = (float*)d_out;

    float* S = nullptr;
    cudaGetSymbolAddress((void**)&S, g_scratch);
    __half* H = nullptr;
    cudaGetSymbolAddress((void**)&H, g_hscr);

    float* cqkv = S + OFF_CQKV;
    float* bcmb = S + OFF_BCMB;
    __half* xh    = H + HOFF_X;
    __half* wch   = H + HOFF_WCOMB;
    __half* wuqh  = H + HOFF_WUQ;
    __half* wukvh = H + HOFF_WUKV;
    __half* woh   = H + HOFF_WO;
    __half* cqh   = H + HOFF_CQ;
    __half* ckvh  = H + HOFF_CKV;
    __half* qlinh = H + HOFF_QLIN;
    __half* kvh   = H + HOFF_KV;
    __half* qfh   = H + HOFF_QF;
    __half* kfh   = H + HOFF_KF;
    __half* vth   = H + HOFF_VT;
    __half* yh    = H + HOFF_Y;

    static cudaStream_t s1 = nullptr;
    static cudaEvent_t e0 = nullptr, eG = nullptr, eQ = nullptr;
    static int init_done = 0;
    if (!init_done) {
        cudaFuncSetAttribute(gemm_h<float>, cudaFuncAttributeMaxDynamicSharedMemorySize, GSMB);
        cudaFuncSetAttribute(gemm_h<__half>, cudaFuncAttributeMaxDynamicSharedMemorySize, GSMB);
        cudaStreamCreateWithFlags(&s1, cudaStreamNonBlocking);
        cudaEventCreateWithFlags(&e0, cudaEventDisableTiming);
        cudaEventCreateWithFlags(&eG, cudaEventDisableTiming);
        cudaEventCreateWithFlags(&eQ, cudaEventDisableTiming);
        init_done = 1;
    }

    // fork side stream from main stream
    cudaEventRecord(e0, 0);
    cudaStreamWaitEvent(s1, e0, 0);

    // side stream: weight conversions not needed by the fused GEMM
    f2h_weights<<<dim3((HSZ_WO / 4 + 255) / 256, 2), 256, 0, s1>>>(
        Wukv_w, wukvh, HSZ_WUKV / 4, Wo_w, woh, HSZ_WO / 4);
    pack_wuq<<<(2048 * DQP + 255) / 256, 256, 0, s1>>>(Wuq_w, wuqh);

    // main stream: x conversion + combined weights + fused GEMM
    f2h_copy<<<(HSZ_X / 4 + 255) / 256, 256>>>(x, xh, HSZ_X / 4);
    pack_comb<<<(NCOMB * DM + 255) / 256, 256>>>(Wdq_w, Wdq_b, Wdkv_w, Wdkv_b, wch, bcmb);
    gemm_h<float><<<dim3(NCOMB / 128, BT / 128), 256, GSMB>>>(
        xh, wch, bcmb, cqkv, BT, NCOMB, DM, DM, NCOMB);
    cudaEventRecord(eG, 0);
    cudaStreamWaitEvent(s1, eG, 0);

    // q branch on side stream
    ln_kernel<<<BT, 256, 0, s1>>>(cqkv, NCOMB, DQ, qn_g, qn_b, cqh, DQP);
    gemm_h<__half><<<dim3(16, BT / 128), 256, GSMB, s1>>>(
        cqh, wuqh, Wuq_b, qlinh, BT, DM, DQP, DQP, DM);
    prep_q_kernel<<<HSZ_F / 256, 256, 0, s1>>>(qlinh, qfh);
    cudaEventRecord(eQ, s1);

    // kv branch on main stream
    ln_kernel<<<BT, 256>>>(cqkv + DQP, NCOMB, DKV, kvn_g, kvn_b, ckvh, DKV);
    gemm_h<__half><<<dim3(24, BT / 128), 256, GSMB>>>(
        ckvh, wukvh, Wukv_b, kvh, BT, 3072, DKV, DKV, 3072);
    prep_kv_kernel<<<dim3(T_ / 32, 32), 256>>>(kvh, cqkv + DQP + DKV, kfh, vth);

    // join, then attention + output projection on main stream
    cudaStreamWaitEvent(0, eQ, 0);
    attn_h<<<dim3(T_ / 64, 32), 128, ASM_TOT>>>(qfh, kfh, vth, yh);
    gemm_h<float><<<dim3(16, BT / 128), 256, GSMB>>>(yh, woh, Wo_b, out, BT, DM, DM, DM, DM);
}

// round 16
// speedup vs baseline: 1.0314x; 1.0314x over previous
#include <cuda_runtime.h>
#include <cuda_fp16.h>
#include <cstdint>

#define B_    2
#define T_    2048
#define NH    16
#define DM    2048
#define DQ    682
#define DQP   704
#define DKV   1024
#define DCKV  1088
#define BT    4096
#define NCOMB 1792            // 704 (padded Wdq) + 1088 (Wdkv)

// ---------------- float scratch ----------------
#define SZ_CQKV  (BT * NCOMB)
#define OFF_CQKV 0
#define OFF_BCMB (OFF_CQKV + SZ_CQKV)
#define OFF_BQR  (OFF_BCMB + NCOMB)
#define SZ_FTOT  (OFF_BQR + DM)
__device__ __align__(1024) float g_scratch[SZ_FTOT];

// ---------------- half scratch ----------------
#define HSZ_X     (BT * DM)
#define HSZ_WCOMB (NCOMB * DM)
#define HSZ_WUQ   (2048 * DQP)
#define HSZ_WUKV  (3072 * DKV)
#define HSZ_WO    (DM * DM)
#define HSZ_CQ    (BT * DQP)
#define HSZ_CKV   (BT * DKV)
#define HSZ_KV    (BT * 3072)
#define HSZ_F     (32 * T_ * 128)
#define HOFF_X     0
#define HOFF_WCOMB (HOFF_X + HSZ_X)
#define HOFF_WUQ   (HOFF_WCOMB + HSZ_WCOMB)
#define HOFF_WUKV  (HOFF_WUQ + HSZ_WUQ)
#define HOFF_WO    (HOFF_WUKV + HSZ_WUKV)
#define HOFF_CQ    (HOFF_WO + HSZ_WO)
#define HOFF_CKV   (HOFF_CQ + HSZ_CQ)
#define HOFF_KV    (HOFF_CKV + HSZ_CKV)
#define HOFF_QF    (HOFF_KV + HSZ_KV)
#define HOFF_KF    (HOFF_QF + HSZ_F)
#define HOFF_VT    (HOFF_KF + HSZ_F)
#define HOFF_Y     (HOFF_VT + HSZ_F)
#define HSZ_TOT    (HOFF_Y + HSZ_F)
__device__ __align__(1024) __half g_hscr[HSZ_TOT];

// ---------------- helpers ----------------
__device__ __forceinline__ float ex2(float x) {
    float r; asm("ex2.approx.f32 %0,%1;" : "=f"(r) : "f"(x)); return r;
}
__device__ __forceinline__ uint32_t f2h2(float hi, float lo) {
    uint32_t u; asm("cvt.rn.f16x2.f32 %0,%1,%2;" : "=r"(u) : "f"(hi), "f"(lo)); return u;
}
__device__ __forceinline__ void mma_f16(float* d, const uint32_t* a, const uint32_t* b) {
    asm volatile(
        "mma.sync.aligned.m16n8k16.row.col.f32.f16.f16.f32 "
        "{%0,%1,%2,%3}, {%4,%5,%6,%7}, {%8,%9}, {%0,%1,%2,%3};\n"
        : "+f"(d[0]), "+f"(d[1]), "+f"(d[2]), "+f"(d[3])
        : "r"(a[0]), "r"(a[1]), "r"(a[2]), "r"(a[3]), "r"(b[0]), "r"(b[1]));
}
__device__ __forceinline__ void ldsm4(uint32_t* r, uint32_t addr) {
    asm volatile("ldmatrix.sync.aligned.m8n8.x4.shared.b16 {%0,%1,%2,%3}, [%4];"
        : "=r"(r[0]), "=r"(r[1]), "=r"(r[2]), "=r"(r[3]) : "r"(addr));
}
__device__ __forceinline__ void cp16(uint32_t dst, const void* src) {
    asm volatile("cp.async.cg.shared.global [%0], [%1], 16;" :: "r"(dst), "l"(src));
}
__device__ __forceinline__ void cp_commit() { asm volatile("cp.async.commit_group;"); }
template<int N> __device__ __forceinline__ void cp_wait() {
    asm volatile("cp.async.wait_group %0;" :: "n"(N));
}

// ---------------- fp16 GEMM: C = A @ W^T + bias ----------------
// BM=128, BN=128, BK=32 halves, 3-stage cp.async, 8 warps, warp tile 64x32, ldmatrix.x4.
// QF=true: scatter half output directly into qf[bh][t][128] layout.
#define G_ST 3
#define AST (128 * 20)
#define GSMB (2 * AST * 4 * G_ST)

template<typename OT, bool QF>
__global__ void __launch_bounds__(256, 2) gemm_h(
    const __half* __restrict__ A, const __half* __restrict__ W,
    const float* __restrict__ bias, OT* __restrict__ C,
    int M, int N, int K, int lda, int ldc)
{
    extern __shared__ uint32_t smu[];
    const uint32_t smA_u = (uint32_t)__cvta_generic_to_shared(smu);
    const uint32_t smB_u = smA_u + G_ST * AST * 4;
    const int tid = threadIdx.x;
    const int m0 = blockIdx.y * 128;
    const int n0 = blockIdx.x * 128;
    const int warp = tid >> 5, lane = tid & 31;
    const int wm = warp & 1, wn = warp >> 1;
    const int gid = lane >> 2, tig = lane & 3;
    const int g = lane >> 3, lr = lane & 7;
    const int arow = (g & 1) * 8 + lr, achk = g >> 1;
    const int brow = (g >> 1) * 8 + lr, bchk = g & 1;
    uint32_t aoff[4], boff[2];
#pragma unroll
    for (int mt = 0; mt < 4; mt++)
        aoff[mt] = (uint32_t)((wm * 64 + mt * 16 + arow) * 80 + achk * 16);
#pragma unroll
    for (int ntp = 0; ntp < 2; ntp++)
        boff[ntp] = (uint32_t)((wn * 32 + ntp * 16 + brow) * 80 + bchk * 16);

    float c[4][4][4];
#pragma unroll
    for (int i = 0; i < 4; i++)
#pragma unroll
        for (int j = 0; j < 4; j++)
#pragma unroll
            for (int r = 0; r < 4; r++) c[i][j][r] = 0.f;

    const int ntile = K / 32;

#define LOAD_STAGE(st, k0) do {                                               \
        const uint32_t ab = smA_u + (st) * (AST * 4);                         \
        const uint32_t bb2 = smB_u + (st) * (AST * 4);                        \
        _Pragma("unroll")                                                     \
        for (int ii = 0; ii < 2; ii++) {                                      \
            const int cid = tid + ii * 256;                                   \
            const int r = cid >> 2, ch = cid & 3;                             \
            cp16(ab + r * 80 + ch * 16,                                       \
                 A + (size_t)(m0 + r) * lda + (k0) + ch * 8);                 \
            cp16(bb2 + r * 80 + ch * 16,                                      \
                 W + (size_t)(n0 + r) * K + (k0) + ch * 8);                   \
        }                                                                     \
    } while (0)

    LOAD_STAGE(0, 0);  cp_commit();
    LOAD_STAGE(1, 32); cp_commit();

    for (int kt = 0; kt < ntile; kt++) {
        cp_wait<1>();
        __syncthreads();
        if (kt + 2 < ntile) { LOAD_STAGE((kt + 2) % 3, (kt + 2) * 32); }
        cp_commit();
        const uint32_t Ab = smA_u + (kt % 3) * (AST * 4);
        const uint32_t Bb = smB_u + (kt % 3) * (AST * 4);
#pragma unroll
        for (int ks = 0; ks < 2; ks++) {
            uint32_t amt[4][4], bb[2][4];
#pragma unroll
            for (int mt = 0; mt < 4; mt++) ldsm4(amt[mt], Ab + aoff[mt] + ks * 32);
#pragma unroll
            for (int ntp = 0; ntp < 2; ntp++) ldsm4(bb[ntp], Bb + boff[ntp] + ks * 32);
#pragma unroll
            for (int mt = 0; mt < 4; mt++)
#pragma unroll
                for (int nt = 0; nt < 4; nt++)
                    mma_f16(c[mt][nt], amt[mt], &bb[nt >> 1][(nt & 1) * 2]);
        }
    }
#undef LOAD_STAGE

#pragma unroll
    for (int mt = 0; mt < 4; mt++) {
        const int row = m0 + wm * 64 + mt * 16 + gid;
#pragma unroll
        for (int nt = 0; nt < 4; nt++) {
            const int col = n0 + wn * 32 + nt * 8 + 2 * tig;
            if (col >= ldc) continue;
            const float b0 = bias[col];
            const float b1 = bias[col + 1];
            const float r00 = c[mt][nt][0] + b0;
            const float r01 = c[mt][nt][1] + b1;
            const float r10 = c[mt][nt][2] + b0;
            const float r11 = c[mt][nt][3] + b1;
            if constexpr (QF) {
                // scatter into qf[(b*16+h)][t][d]; rows row,row+8 share b & h
                const int b = row >> 11, t = row & 2047;
                const int h = col >> 7, d = col & 127;
                __half* dst = (__half*)C + (((size_t)(b * 16 + h) * T_ + t) * 128 + d);
                *(uint32_t*)dst = f2h2(r01, r00);
                *(uint32_t*)(dst + 8 * 128) = f2h2(r11, r10);
            } else if constexpr (sizeof(OT) == 4) {
                *(float2*)((float*)C + (size_t)row * ldc + col) = make_float2(r00, r01);
                *(float2*)((float*)C + (size_t)(row + 8) * ldc + col) = make_float2(r10, r11);
            } else {
                *(uint32_t*)((__half*)C + (size_t)row * ldc + col) = f2h2(r01, r00);
                *(uint32_t*)((__half*)C + (size_t)(row + 8) * ldc + col) = f2h2(r11, r10);
            }
        }
    }
}

// ---------------- conversion / prep kernels ----------------
__global__ void f2h_copy(const float* __restrict__ src, __half* __restrict__ dst, int n4)
{
    const int i = blockIdx.x * 256 + threadIdx.x;
    if (i >= n4) return;
    float4 v = ((const float4*)src)[i];
    uint2 u;
    u.x = f2h2(v.y, v.x);
    u.y = f2h2(v.w, v.z);
    ((uint2*)dst)[i] = u;
}

__global__ void f2h_weights(const float* w0, __half* d0, int n0,
                            const float* w1, __half* d1, int n1)
{
    const int i = blockIdx.x * 256 + threadIdx.x;
    const float* s; __half* d; int n;
    if (blockIdx.y == 0) { s = w0; d = d0; n = n0; }
    else                 { s = w1; d = d1; n = n1; }
    if (i >= n) return;
    float4 v = ((const float4*)s)[i];
    uint2 u;
    u.x = f2h2(v.y, v.x);
    u.y = f2h2(v.w, v.z);
    ((uint2*)d)[i] = u;
}

// combined [Wdq; pad; Wdkv] weights (half, vectorized) + bias (float)
__global__ void pack_comb(const float* __restrict__ wdq, const float* __restrict__ wdq_b,
                          const float* __restrict__ wdkv, const float* __restrict__ wdkv_b,
                          __half* __restrict__ wc, float* __restrict__ bc)
{
    const int idx = blockIdx.x * 256 + threadIdx.x;
    if (idx < NCOMB) {
        float bv = 0.f;
        if (idx < DQ) bv = wdq_b[idx];
        else if (idx >= DQP) bv = wdkv_b[idx - DQP];
        bc[idx] = bv;
    }
    if (idx >= NCOMB * DM / 4) return;
    const int r = idx >> 9;              // DM/4 = 512 chunks per row
    const int k = (idx & 511) * 4;
    uint2 u;
    if (r < DQ) {
        const float4 v = *(const float4*)(wdq + (size_t)r * DM + k);
        u.x = f2h2(v.y, v.x); u.y = f2h2(v.w, v.z);
    } else if (r >= DQP) {
        const float4 v = *(const float4*)(wdkv + (size_t)(r - DQP) * DM + k);
        u.x = f2h2(v.y, v.x); u.y = f2h2(v.w, v.z);
    } else {
        u.x = 0u; u.y = 0u;
    }
    *(uint2*)(wc + (size_t)r * DM + k) = u;
}

// Wuq with rotary + scale*log2e folded into the weights (rotation is t-independent:
// angle = f(head, dim) only — the reference's shape[1] quirk). Also rotates the bias.
__global__ void pack_wuq_rot(const float* __restrict__ w, const float* __restrict__ bias,
                             __half* __restrict__ wp, float* __restrict__ bp)
{
    const float SC = 0.08838834764831845f * 1.4426950408889634f;
    const int idx = blockIdx.x * 256 + threadIdx.x;
    if (idx < 2048) {
        const int h = idx >> 7, d = idx & 127;
        float bv;
        if (d < 64) {
            bv = bias[idx];
        } else {
            const int i = (d - 64) & 31;
            const float inv = __expf(-(float)i * 0.2878231366242557f);
            float sn, cs;
            __sincosf((float)h * inv, &sn, &cs);
            const float b1 = bias[h * 128 + 64 + i];
            const float b2 = bias[h * 128 + 96 + i];
            bv = (d < 96) ? (b1 * cs + b2 * sn) : (b2 * cs - b1 * sn);
        }
        bp[idx] = bv * SC;
    }
    if (idx >= 2048 * DQP) return;
    const int n = idx / DQP, k = idx - n * DQP;
    if (k >= DQ) { wp[idx] = __float2half(0.f); return; }
    const int h = n >> 7, d = n & 127;
    float wv;
    if (d < 64) {
        wv = w[(size_t)n * DQ + k];
    } else {
        const int i = (d - 64) & 31;
        const float inv = __expf(-(float)i * 0.2878231366242557f);
        float sn, cs;
        __sincosf((float)h * inv, &sn, &cs);
        const float w1 = w[(size_t)(h * 128 + 64 + i) * DQ + k];
        const float w2 = w[(size_t)(h * 128 + 96 + i) * DQ + k];
        wv = (d < 96) ? (w1 * cs + w2 * sn) : (w2 * cs - w1 * sn);
    }
    wp[idx] = __float2half(wv * SC);
}

__global__ void ln_kernel(const float* __restrict__ X, int stride, int n,
                          const float* __restrict__ g, const float* __restrict__ bb,
                          __half* __restrict__ out, int ostride)
{
    const int row = blockIdx.x;
    const float* xr = X + (size_t)row * stride;
    __half* orow = out + (size_t)row * ostride;
    const int tid = threadIdx.x;
    float s = 0.f, ss = 0.f;
    for (int i = tid; i < n; i += 256) { float v = xr[i]; s += v; ss += v * v; }
#pragma unroll
    for (int o = 16; o > 0; o >>= 1) {
        s  += __shfl_down_sync(0xffffffffu, s, o);
        ss += __shfl_down_sync(0xffffffffu, ss, o);
    }
    __shared__ float rs[8], rss[8];
    __shared__ float sh_mu, sh_rstd;
    if ((tid & 31) == 0) { rs[tid >> 5] = s; rss[tid >> 5] = ss; }
    __syncthreads();
    if (tid == 0) {
        float ts = 0.f, tss = 0.f;
#pragma unroll
        for (int i = 0; i < 8; i++) { ts += rs[i]; tss += rss[i]; }
        const float mu = ts / n;
        sh_mu = mu;
        sh_rstd = rsqrtf(tss / n - mu * mu + 1e-5f);
    }
    __syncthreads();
    const float mu = sh_mu, rstd = sh_rstd;
    for (int i = tid; i < n; i += 256)
        orow[i] = __float2half((xr[i] - mu) * rstd * g[i] + bb[i]);
    for (int i = n + tid; i < ostride; i += 256)
        orow[i] = __float2half(0.f);
}

__global__ void prep_kv_kernel(const __half* __restrict__ kv, const float* __restrict__ krs,
                               __half* __restrict__ kf, __half* __restrict__ vt)
{
    __shared__ __half vs[32][136];
    const int bh = blockIdx.y, tile = blockIdx.x;
    const int b = bh >> 4, h = bh & 15;
    const int tid = threadIdx.x;
    for (int e = tid; e < 32 * 128; e += 256) {
        const int tl = e >> 7, d = e & 127;
        const int t = tile * 32 + tl;
        const size_t row = (size_t)(b * T_ + t);
        const __half* kvrow = kv + row * 3072 + h * 192;
        const __half kvv = (d < 64) ? kvrow[d] : __float2half(krs[row * NCOMB + (d - 64)]);
        kf[((size_t)bh * T_ + t) * 128 + d] = kvv;
        vs[tl][d] = kvrow[64 + d];
    }
    __syncthreads();
    for (int c = tid; c < 512; c += 256) {
        const int d = c >> 2, q = c & 3;
        uint4 u;
        __half* tgt = (__half*)&u;
#pragma unroll
        for (int j = 0; j < 8; j++) tgt[j] = vs[8 * q + j][d];
        *(uint4*)(vt + ((size_t)bh * 128 + d) * T_ + tile * 32 + 8 * q) = u;
    }
}

// ---------------- fp16 causal flash attention with ldmatrix ----------------
#define KROWB 272
#define VROWB 144
#define SMK_B (64 * KROWB)
#define SMV_B (128 * VROWB)
#define ASM_TOT (SMK_B + SMV_B)

__global__ __launch_bounds__(128, 3) void attn_h(
    const __half* __restrict__ qf, const __half* __restrict__ kf,
    const __half* __restrict__ vt, __half* __restrict__ y)
{
    extern __shared__ uint32_t asw[];
    const int tid = threadIdx.x;
    const int warp = tid >> 5, lane = tid & 31;
    const int gid = lane >> 2, tig = lane & 3;
    const int g = lane >> 3, lr = lane & 7;
    const int arow = (g & 1) * 8 + lr, achk = g >> 1;
    const int brow = (g >> 1) * 8 + lr, bchk = g & 1;
    const int qt = (int)gridDim.x - 1 - (int)blockIdx.x;
    const int bh = blockIdx.y;
    const int qb = qt * 64;
    const __half* Qg = qf + ((size_t)bh * T_ + qb) * 128;
    const __half* Kg = kf + (size_t)bh * T_ * 128;
    const __half* Vg = vt + (size_t)bh * 128 * T_;
    const uint32_t smb = (uint32_t)__cvta_generic_to_shared(asw);
    const uint32_t ks_u = smb;
    const uint32_t vs_u = smb + SMK_B;
    const uint32_t ka_off = (uint32_t)((warp * 16 + arow) * KROWB + achk * 16);
    const uint32_t kb_off = (uint32_t)(brow * KROWB + bchk * 16);
    const uint32_t vb_off = (uint32_t)(brow * VROWB + bchk * 16);

#pragma unroll
    for (int i = 0; i < 8; i++) {
        const int c = tid + i * 128;
        const int r = c >> 4, ch = c & 15;
        cp16(ks_u + r * KROWB + ch * 16, Qg + (size_t)r * 128 + ch * 8);
    }
    cp_commit(); cp_wait<0>();
    __syncthreads();
    uint32_t qa[8][4];
#pragma unroll
    for (int kk = 0; kk < 8; kk++) ldsm4(qa[kk], ks_u + ka_off + kk * 32);
    __syncthreads();

#define LOAD_K(kt) do {                                                       \
        const __half* Kt = Kg + (size_t)(kt) * 64 * 128;                      \
        _Pragma("unroll")                                                     \
        for (int i = 0; i < 8; i++) {                                         \
            const int c = tid + i * 128;                                      \
            const int r = c >> 4, ch = c & 15;                                \
            cp16(ks_u + r * KROWB + ch * 16, Kt + (size_t)r * 128 + ch * 8);  \
        }                                                                     \
    } while (0)
#define LOAD_V(kt) do {                                                       \
        _Pragma("unroll")                                                     \
        for (int i = 0; i < 8; i++) {                                         \
            const int c = tid + i * 128;                                      \
            const int r = c >> 3, ch = c & 7;                                 \
            cp16(vs_u + r * VROWB + ch * 16,                                  \
                 Vg + (size_t)r * T_ + (kt) * 64 + ch * 8);                   \
        }                                                                     \
    } while (0)

    LOAD_K(0); cp_commit();
    LOAD_V(0); cp_commit();

    float o[16][4];
#pragma unroll
    for (int i = 0; i < 16; i++)
#pragma unroll
        for (int j = 0; j < 4; j++) o[i][j] = 0.f;
    float l0 = 0.f, l1 = 0.f;
    const int row0 = qb + warp * 16 + gid;
    const int row1 = row0 + 8;

    for (int kt = 0; kt <= qt; kt++) {
        cp_wait<1>();
        __syncthreads();

        float s[8][4];
#pragma unroll
        for (int nt = 0; nt < 8; nt++)
#pragma unroll
            for (int r = 0; r < 4; r++) s[nt][r] = 0.f;
#pragma unroll
        for (int ntp = 0; ntp < 4; ntp++) {
            const uint32_t base = ks_u + kb_off + (uint32_t)(ntp * 16 * KROWB);
#pragma unroll
            for (int kk = 0; kk < 8; kk++) {
                uint32_t kb[4];
                ldsm4(kb, base + kk * 32);
                mma_f16(s[2 * ntp],     qa[kk], &kb[0]);
                mma_f16(s[2 * ntp + 1], qa[kk], &kb[2]);
            }
        }
        __syncthreads();
        if (kt < qt) { LOAD_K(kt + 1); }
        cp_commit();

        if (kt == qt) {
            const int kb = kt * 64;
#pragma unroll
            for (int nt = 0; nt < 8; nt++) {
                const int col = kb + 8 * nt + 2 * tig;
                if (col > row0)     s[nt][0] = -1e30f;
                if (col + 1 > row0) s[nt][1] = -1e30f;
                if (col > row1)     s[nt][2] = -1e30f;
                if (col + 1 > row1) s[nt][3] = -1e30f;
            }
        }
        uint32_t ph[8][2];
#pragma unroll
        for (int nt = 0; nt < 8; nt++) {
            const float p0 = ex2(s[nt][0]);
            const float p1 = ex2(s[nt][1]);
            const float p2 = ex2(s[nt][2]);
            const float p3 = ex2(s[nt][3]);
            l0 += p0 + p1;
            l1 += p2 + p3;
            ph[nt][0] = f2h2(p1, p0);
            ph[nt][1] = f2h2(p3, p2);
        }

        cp_wait<1>();
        __syncthreads();
#pragma unroll
        for (int kk = 0; kk < 4; kk++) {
            uint32_t pa[4];
            pa[0] = ph[2 * kk][0];
            pa[1] = ph[2 * kk][1];
            pa[2] = ph[2 * kk + 1][0];
            pa[3] = ph[2 * kk + 1][1];
#pragma unroll
            for (int ntp = 0; ntp < 8; ntp++) {
                uint32_t vb[4];
                ldsm4(vb, vs_u + vb_off + (uint32_t)(ntp * 16 * VROWB) + kk * 32);
                mma_f16(o[2 * ntp],     pa, &vb[0]);
                mma_f16(o[2 * ntp + 1], pa, &vb[2]);
            }
        }
        __syncthreads();
        if (kt < qt) { LOAD_V(kt + 1); }
        cp_commit();
    }
#undef LOAD_K
#undef LOAD_V

    l0 += __shfl_xor_sync(0xffffffffu, l0, 1);
    l0 += __shfl_xor_sync(0xffffffffu, l0, 2);
    l1 += __shfl_xor_sync(0xffffffffu, l1, 1);
    l1 += __shfl_xor_sync(0xffffffffu, l1, 2);
    const float i0 = 1.f / l0, i1 = 1.f / l1;
    const int b = bh >> 4, h = bh & 15;
    __half* y0 = y + ((size_t)(b * T_ + row0)) * 2048 + h * 128;
    __half* y1 = y + ((size_t)(b * T_ + row1)) * 2048 + h * 128;
#pragma unroll
    for (int nt = 0; nt < 16; nt++) {
        const int col = 8 * nt + 2 * tig;
        *(uint32_t*)(y0 + col) = f2h2(o[nt][1] * i0, o[nt][0] * i0);
        *(uint32_t*)(y1 + col) = f2h2(o[nt][3] * i1, o[nt][2] * i1);
    }
}

// ---------------- launch ----------------
extern "C" void kernel_launch(void* const* d_in, const int* in_sizes, int n_in,
                              void* d_out, int out_size)
{
    const float* x      = (const float*)d_in[0];
    const float* Wdq_w  = (const float*)d_in[1];
    const float* Wdq_b  = (const float*)d_in[2];
    const float* qn_g   = (const float*)d_in[3];
    const float* qn_b   = (const float*)d_in[4];
    const float* Wuq_w  = (const float*)d_in[5];
    const float* Wuq_b  = (const float*)d_in[6];
    const float* Wdkv_w = (const float*)d_in[7];
    const float* Wdkv_b = (const float*)d_in[8];
    const float* kvn_g  = (const float*)d_in[9];
    const float* kvn_b  = (const float*)d_in[10];
    const float* Wukv_w = (const float*)d_in[11];
    const float* Wukv_b = (const float*)d_in[12];
    const float* Wo_w   = (const float*)d_in[13];
    const float* Wo_b   = (const float*)d_in[14];
    float* out = (float*)d_out;

    float* S = nullptr;
    cudaGetSymbolAddress((void**)&S, g_scratch);
    __half* H = nullptr;
    cudaGetSymbolAddress((void**)&H, g_hscr);

    float* cqkv = S + OFF_CQKV;
    float* bcmb = S + OFF_BCMB;
    float* bqr  = S + OFF_BQR;
    __half* xh    = H + HOFF_X;
    __half* wch   = H + HOFF_WCOMB;
    __half* wuqh  = H + HOFF_WUQ;
    __half* wukvh = H + HOFF_WUKV;
    __half* woh   = H + HOFF_WO;
    __half* cqh   = H + HOFF_CQ;
    __half* ckvh  = H + HOFF_CKV;
    __half* kvh   = H + HOFF_KV;
    __half* qfh   = H + HOFF_QF;
    __half* kfh   = H + HOFF_KF;
    __half* vth   = H + HOFF_VT;
    __half* yh    = H + HOFF_Y;

    static cudaStream_t s1 = nullptr;
    static cudaEvent_t e0 = nullptr, eG = nullptr, eQ = nullptr;
    static int init_done = 0;
    if (!init_done) {
        cudaFuncSetAttribute((const void*)&gemm_h<float, false>,
                             cudaFuncAttributeMaxDynamicSharedMemorySize, GSMB);
        cudaFuncSetAttribute((const void*)&gemm_h<__half, false>,
                             cudaFuncAttributeMaxDynamicSharedMemorySize, GSMB);
        cudaFuncSetAttribute((const void*)&gemm_h<__half, true>,
                             cudaFuncAttributeMaxDynamicSharedMemorySize, GSMB);
        cudaStreamCreateWithFlags(&s1, cudaStreamNonBlocking);
        cudaEventCreateWithFlags(&e0, cudaEventDisableTiming);
        cudaEventCreateWithFlags(&eG, cudaEventDisableTiming);
        cudaEventCreateWithFlags(&eQ, cudaEventDisableTiming);
        init_done = 1;
    }

    // fork side stream
    cudaEventRecord(e0, 0);
    cudaStreamWaitEvent(s1, e0, 0);

    // side stream: weight prep not needed by the fused GEMM
    f2h_weights<<<dim3((HSZ_WO / 4 + 255) / 256, 2), 256, 0, s1>>>(
        Wukv_w, wukvh, HSZ_WUKV / 4, Wo_w, woh, HSZ_WO / 4);
    pack_wuq_rot<<<(2048 * DQP + 255) / 256, 256, 0, s1>>>(Wuq_w, Wuq_b, wuqh, bqr);

    // main stream: x conversion + combined weights + fused GEMM
    f2h_copy<<<(HSZ_X / 4 + 255) / 256, 256>>>(x, xh, HSZ_X / 4);
    pack_comb<<<(NCOMB * DM / 4 + 255) / 256, 256>>>(Wdq_w, Wdq_b, Wdkv_w, Wdkv_b, wch, bcmb);
    gemm_h<float, false><<<dim3(NCOMB / 128, BT / 128), 256, GSMB>>>(
        xh, wch, bcmb, cqkv, BT, NCOMB, DM, DM, NCOMB);
    cudaEventRecord(eG, 0);
    cudaStreamWaitEvent(s1, eG, 0);

    // q branch on side stream: LN -> rotated GEMM scattering directly to qf
    ln_kernel<<<BT, 256, 0, s1>>>(cqkv, NCOMB, DQ, qn_g, qn_b, cqh, DQP);
    gemm_h<__half, true><<<dim3(16, BT / 128), 256, GSMB, s1>>>(
        cqh, wuqh, bqr, qfh, BT, DM, DQP, DQP, DM);
    cudaEventRecord(eQ, s1);

    // kv branch on main stream
    ln_kernel<<<BT, 256>>>(cqkv + DQP, NCOMB, DKV, kvn_g, kvn_b, ckvh, DKV);
    gemm_h<__half, false><<<dim3(24, BT / 128), 256, GSMB>>>(
        ckvh, wukvh, Wukv_b, kvh, BT, 3072, DKV, DKV, 3072);
    prep_kv_kernel<<<dim3(T_ / 32, 32), 256>>>(kvh, cqkv + DQP + DKV, kfh, vth);

    // join, then attention + output projection
    cudaStreamWaitEvent(0, eQ, 0);
    attn_h<<<dim3(T_ / 64, 32), 128, ASM_TOT>>>(qfh, kfh, vth, yh);
    gemm_h<float, false><<<dim3(16, BT / 128), 256, GSMB>>>(yh, woh, Wo_b, out, BT, DM, DM, DM, DM);
}